// round 12
// baseline (speedup 1.0000x reference)
#include <cuda_runtime.h>

// Scratch (no allocations allowed): k = conv taps. (g_s eliminated by fusion.)
__device__ __align__(16) float g_k[4 * 16 * 1024];    // [b][u][m]

#define TAPS 16
#define BQ 4
#define LQ 2048
#define DMQ 1024
#define NQ 64
#define CUTOFF (-30.0f)   // u*log_A below this => tap < e^-30 of signal

// ---------------------------------------------------------------------------
// K12 (fused): per block (b, ug, m-tile):
//   Phase A: s[ui][n] = (dot(x[b,u,:], W_B[n,:]) + b_B[n]) * exp(u*log_A[n])
//            for the block's 4 u-rows (u = ug*4+ui), n < cnt[ui] (runtime
//            cutoff; active set is a prefix for monotone log_A). Flattened
//            (ui,n) list, warp-strided, 8 front-batched LDG.128 per dot.
//   Phase B: k[b,u,m] = sum_{n<cnt} s[ui][n] * C[n,m]  (sparsity = bound).
// grid = (16 m-tiles of 64, 16 (b,ug)), block = 256, smem = 17 KB.
// ---------------------------------------------------------------------------
__global__ void __launch_bounds__(256) s4_k12(const float* __restrict__ x,
                                              const float* __restrict__ W_B,
                                              const float* __restrict__ b_B,
                                              const float* __restrict__ C,
                                              const float* __restrict__ log_A) {
    cudaTriggerProgrammaticLaunchCompletion();

    int b  = blockIdx.y >> 2;
    int ug = blockIdx.y & 3;
    int u0 = ug * 4;
    int tid = threadIdx.x;
    int w = tid >> 5;
    int lane = tid & 31;

    __shared__ float4 xs[4][DMQ / 4];    // 4 x-rows, 16 KB
    __shared__ float s_sm[4][NQ];

    // Active counts per u-row (prefix property: log_A monotone decreasing).
    int cnt[4], pref[5];
    pref[0] = 0;
    #pragma unroll
    for (int ui = 0; ui < 4; ui++) {
        int u = u0 + ui;
        int c = 0;
        #pragma unroll
        for (int n = 0; n < NQ; n++)
            if ((float)u * log_A[n] >= CUTOFF) c = n + 1;
        cnt[ui] = c;
        pref[ui + 1] = pref[ui] + c;
    }
    int T = pref[4];

    // Stage the 4 x rows (each thread: one float4 per row).
    #pragma unroll
    for (int ui = 0; ui < 4; ui++) {
        const float4* xr = reinterpret_cast<const float4*>(
            x + ((size_t)b * LQ + (u0 + ui)) * DMQ);
        xs[ui][tid] = xr[tid];
    }
    __syncthreads();

    // ---- Phase A: warp-strided over the T active dots ----
    for (int i = w; i < T; i += 8) {
        int ui = (i >= pref[1]) + (i >= pref[2]) + (i >= pref[3]);
        int n = i - pref[ui];
        int u = u0 + ui;

        const float4* wr = reinterpret_cast<const float4*>(W_B + (size_t)n * DMQ);
        float4 wv[8];
        #pragma unroll
        for (int j = 0; j < 8; j++) wv[j] = wr[lane + 32 * j];   // front-batched

        float p0 = 0.0f, p1 = 0.0f;
        #pragma unroll
        for (int j = 0; j < 8; j++) {
            float4 a = xs[ui][lane + 32 * j];
            p0 += a.x * wv[j].x + a.y * wv[j].y;
            p1 += a.z * wv[j].z + a.w * wv[j].w;
        }
        float p = p0 + p1;
        #pragma unroll
        for (int off = 16; off; off >>= 1) p += __shfl_xor_sync(0xFFFFFFFFu, p, off);

        if (lane == 0)
            s_sm[ui][n] = (p + b_B[n]) * expf((float)u * log_A[n]);
    }
    __syncthreads();

    // ---- Phase B: thread = (u-row, m). Dense loop, trip bound = cnt. ----
    int urow = tid >> 6;
    int m = blockIdx.x * 64 + (tid & 63);
    int nc = cnt[urow];

    float acc = 0.0f;
    const float* sr = s_sm[urow];
    #pragma unroll 8
    for (int n = 0; n < nc; n++)
        acc += sr[n] * C[(size_t)n * DMQ + m];

    g_k[((size_t)b * TAPS + u0 + urow) * DMQ + m] = acc;
}

// ---------------------------------------------------------------------------
// K3: 16-tap per-channel causal FIR + D skip, packed f32x2 math.
// Rolling 16-slot window, t-tile = 32 (halo traffic 1.47x).
// PDL secondary: x history + D loaded pre-sync, taps post-sync.
// __launch_bounds__(256,3). grid = (2, 64, 4) = 512 blocks. ~DRAM floor.
// ---------------------------------------------------------------------------
typedef unsigned long long u64t;

__device__ __forceinline__ u64t ffma2(u64t a, u64t b, u64t c) {
    u64t d;
    asm("fma.rn.f32x2 %0, %1, %2, %3;" : "=l"(d) : "l"(a), "l"(b), "l"(c));
    return d;
}
__device__ __forceinline__ u64t fmul2(u64t a, u64t b) {
    u64t d;
    asm("mul.rn.f32x2 %0, %1, %2;" : "=l"(d) : "l"(a), "l"(b));
    return d;
}

__global__ void __launch_bounds__(256, 3) s4_k3(const float* __restrict__ x,
                                                const float* __restrict__ D,
                                                float* __restrict__ out) {
    const int S = DMQ / 2;                       // row stride in pairs
    int c  = blockIdx.x * 256 + threadIdx.x;     // 0..511 channel pair
    int t0 = blockIdx.y * 32;
    int b  = blockIdx.z;

    const u64t* xp = reinterpret_cast<const u64t*>(x) + (size_t)b * LQ * S + c;
    u64t dp = reinterpret_cast<const u64t*>(D)[c];

    // Pre-sync: history x[t0-15 .. t0-1] into rolling slots 0..14
    u64t wbuf[16];
    #pragma unroll
    for (int i = 0; i < 15; i++) {
        int t = t0 - 15 + i;
        wbuf[i] = (t >= 0) ? xp[(size_t)t * S] : 0ull;   // 0x0 == {+0.f,+0.f}
    }

    cudaGridDependencySynchronize();             // wait for K12's g_k

    const u64t* kp = reinterpret_cast<const u64t*>(g_k) + (size_t)b * TAPS * S + c;
    u64t kr[TAPS];
    #pragma unroll
    for (int u = 0; u < TAPS; u++) kr[u] = kp[(size_t)u * S];

    u64t* op = reinterpret_cast<u64t*>(out) + (size_t)b * LQ * S + c;

    #pragma unroll
    for (int j = 0; j < 32; j++) {
        u64t xcur = xp[(size_t)(t0 + j) * S];
        wbuf[(15 + j) & 15] = xcur;              // overwrites t0+j-16 (dead)
        u64t a = fmul2(xcur, dp);                // D skip
        #pragma unroll
        for (int u = 0; u < TAPS; u++)
            a = ffma2(kr[u], wbuf[(15 + j - u) & 15], a);
        op[(size_t)(t0 + j) * S] = a;
    }
}

// ---------------------------------------------------------------------------
extern "C" void kernel_launch(void* const* d_in, const int* in_sizes, int n_in,
                              void* d_out, int out_size) {
    const float* x     = (const float*)d_in[0];   // (4, 2048, 1024)
    const float* W_B   = (const float*)d_in[1];   // (64, 1024)
    const float* b_B   = (const float*)d_in[2];   // (64,)
    const float* C     = (const float*)d_in[3];   // (64, 1024)
    const float* D     = (const float*)d_in[4];   // (1024,)
    const float* log_A = (const float*)d_in[5];   // (64,)
    float* out = (float*)d_out;

    s4_k12<<<dim3(16, 16), 256>>>(x, W_B, b_B, C, log_A);

    // K3 (PDL secondary to K12; plain fallback)
    cudaLaunchAttribute attr[1];
    attr[0].id = cudaLaunchAttributeProgrammaticStreamSerialization;
    attr[0].val.programmaticStreamSerializationAllowed = 1;

    cudaLaunchConfig_t cfg = {};
    cfg.gridDim  = dim3(2, 64, 4);
    cfg.blockDim = dim3(256, 1, 1);
    cfg.stream = 0;
    cfg.attrs = attr;
    cfg.numAttrs = 1;
    cudaError_t e = cudaLaunchKernelEx(&cfg, s4_k3, x, D, (float*)out);
    if (e != cudaSuccess) {
        (void)cudaGetLastError();
        s4_k3<<<dim3(2, 64, 4), 256>>>(x, D, out);
    }
}

// round 14
// speedup vs baseline: 1.2877x; 1.2877x over previous
#include <cuda_runtime.h>
#include <cstdint>

// Scratch (no allocations allowed): k = conv taps. (s lives in cluster smem.)
__device__ __align__(16) float g_k[4 * 16 * 1024];    // [b][u][m]

#define TAPS 16
#define BQ 4
#define LQ 2048
#define DMQ 1024
#define NQ 64
#define CUTOFF (-30.0f)   // u*log_A below this => tap < e^-30 of signal
#define CL 8              // cluster size (blocks along x)

// Remote-smem scalar store (cluster rank r), for s broadcast.
__device__ __forceinline__ void st_cluster_f32(unsigned int saddr, int r, float v) {
    unsigned int remote;
    asm volatile("mapa.shared::cluster.u32 %0, %1, %2;"
                 : "=r"(remote) : "r"(saddr), "r"(r));
    asm volatile("st.shared::cluster.f32 [%0], %1;"
                 :: "r"(remote), "f"(v) : "memory");
}

// ---------------------------------------------------------------------------
// K12 (fused, cluster-cooperative): cluster = 8 m-tile blocks of one (b,ug).
//  Phase A: the cluster's 64 warps split the T<=80 active dots (<=2 each,
//           no serialization); each s value is DSMEM-broadcast to all 8
//           blocks' smem. barrier.cluster orders the writes.
//  Phase B: k[b,u,m] = sum_{n<cnt(u)} s[ui][n] * C[n,m]  (bound, no guards).
//  PDL trigger AFTER the g_k store (fixes the R8-R12 entry-trigger race).
// grid = (16 m-tiles of 64, 16 (b,ug)), block = 256, cluster (8,1,1).
// ---------------------------------------------------------------------------
__global__ void __launch_bounds__(256) __cluster_dims__(CL, 1, 1)
s4_k12(const float* __restrict__ x,
       const float* __restrict__ W_B,
       const float* __restrict__ b_B,
       const float* __restrict__ C,
       const float* __restrict__ log_A) {
    int b  = blockIdx.y >> 2;
    int ug = blockIdx.y & 3;
    int u0 = ug * 4;
    int tid = threadIdx.x;
    int w = tid >> 5;
    int lane = tid & 31;
    int rank = blockIdx.x & (CL - 1);    // cluster rank (contiguous along x)

    __shared__ float4 xs[4][DMQ / 4];    // the 4 x rows, 16 KB
    __shared__ float s_sm[4][NQ];

    // Active-prefix counts per u-row (runtime cutoff on actual log_A).
    int cnt[4] = {0, 0, 0, 0};
    #pragma unroll
    for (int n = 0; n < NQ; n++) {
        float la = log_A[n];
        #pragma unroll
        for (int ui = 0; ui < 4; ui++)
            if ((float)(u0 + ui) * la >= CUTOFF) cnt[ui] = n + 1;
    }
    int pref[5];
    pref[0] = 0;
    #pragma unroll
    for (int ui = 0; ui < 4; ui++) pref[ui + 1] = pref[ui] + cnt[ui];
    int T = pref[4];

    // Stage the 4 x rows locally (any warp can then compute any dot).
    #pragma unroll
    for (int ui = 0; ui < 4; ui++) {
        const float4* xr = reinterpret_cast<const float4*>(
            x + ((size_t)b * LQ + (u0 + ui)) * DMQ);
        xs[ui][tid] = xr[tid];
    }
    __syncthreads();

    // ---- Phase A: cluster-distributed dots (<=2 per warp) ----
    for (int i = rank * 8 + w; i < T; i += CL * 8) {
        int ui = (i >= pref[1]) + (i >= pref[2]) + (i >= pref[3]);
        int n = i - pref[ui];

        const float4* wr = reinterpret_cast<const float4*>(W_B + (size_t)n * DMQ);
        float4 wv[8];
        #pragma unroll
        for (int j = 0; j < 8; j++) wv[j] = wr[lane + 32 * j];   // front-batched

        float p0 = 0.0f, p1 = 0.0f;
        #pragma unroll
        for (int j = 0; j < 8; j++) {
            float4 a = xs[ui][lane + 32 * j];
            p0 += a.x * wv[j].x + a.y * wv[j].y;
            p1 += a.z * wv[j].z + a.w * wv[j].w;
        }
        float p = p0 + p1;
        #pragma unroll
        for (int off = 16; off; off >>= 1) p += __shfl_xor_sync(0xFFFFFFFFu, p, off);

        if (lane == 0) {
            float sval = (p + b_B[n]) * expf((float)(u0 + ui) * log_A[n]);
            unsigned int saddr = (unsigned int)__cvta_generic_to_shared(&s_sm[ui][n]);
            #pragma unroll
            for (int r = 0; r < CL; r++) st_cluster_f32(saddr, r, sval);
        }
    }

    // Cluster barrier: orders the DSMEM s-broadcast before Phase B reads.
    asm volatile("barrier.cluster.arrive.aligned;" ::: "memory");
    asm volatile("barrier.cluster.wait.aligned;" ::: "memory");

    // ---- Phase B: thread = (u-row, m). Dense loop, trip bound = cnt. ----
    int urow = tid >> 6;
    int m = blockIdx.x * 64 + (tid & 63);
    int nc = cnt[urow];

    float acc = 0.0f;
    const float* sr = s_sm[urow];
    #pragma unroll 8
    for (int n = 0; n < nc; n++)
        acc += sr[n] * C[(size_t)n * DMQ + m];

    g_k[((size_t)b * TAPS + u0 + urow) * DMQ + m] = acc;

    cudaTriggerProgrammaticLaunchCompletion();   // AFTER the store (race fix)
}

// ---------------------------------------------------------------------------
// K3: 16-tap per-channel causal FIR + D skip, packed f32x2 math.
// Rolling 16-slot window, t-tile = 32 (halo 1.47x). PDL secondary:
// x history + D pre-sync (overlaps K12 drain), taps post-sync.
// __launch_bounds__(256,3). grid = (2, 64, 4) = 512 blocks. ~DRAM floor.
// ---------------------------------------------------------------------------
typedef unsigned long long u64t;

__device__ __forceinline__ u64t ffma2(u64t a, u64t b, u64t c) {
    u64t d;
    asm("fma.rn.f32x2 %0, %1, %2, %3;" : "=l"(d) : "l"(a), "l"(b), "l"(c));
    return d;
}
__device__ __forceinline__ u64t fmul2(u64t a, u64t b) {
    u64t d;
    asm("mul.rn.f32x2 %0, %1, %2;" : "=l"(d) : "l"(a), "l"(b));
    return d;
}

__global__ void __launch_bounds__(256, 3) s4_k3(const float* __restrict__ x,
                                                const float* __restrict__ D,
                                                float* __restrict__ out) {
    const int S = DMQ / 2;                       // row stride in pairs
    int c  = blockIdx.x * 256 + threadIdx.x;     // 0..511 channel pair
    int t0 = blockIdx.y * 32;
    int b  = blockIdx.z;

    const u64t* xp = reinterpret_cast<const u64t*>(x) + (size_t)b * LQ * S + c;
    u64t dp = reinterpret_cast<const u64t*>(D)[c];

    // Pre-sync: history x[t0-15 .. t0-1] into rolling slots 0..14
    u64t wbuf[16];
    #pragma unroll
    for (int i = 0; i < 15; i++) {
        int t = t0 - 15 + i;
        wbuf[i] = (t >= 0) ? xp[(size_t)t * S] : 0ull;   // 0x0 == {+0.f,+0.f}
    }

    cudaGridDependencySynchronize();             // wait for K12's g_k

    const u64t* kp = reinterpret_cast<const u64t*>(g_k) + (size_t)b * TAPS * S + c;
    u64t kr[TAPS];
    #pragma unroll
    for (int u = 0; u < TAPS; u++) kr[u] = kp[(size_t)u * S];

    u64t* op = reinterpret_cast<u64t*>(out) + (size_t)b * LQ * S + c;

    #pragma unroll
    for (int j = 0; j < 32; j++) {
        u64t xcur = xp[(size_t)(t0 + j) * S];
        wbuf[(15 + j) & 15] = xcur;              // overwrites t0+j-16 (dead)
        u64t a = fmul2(xcur, dp);                // D skip
        #pragma unroll
        for (int u = 0; u < TAPS; u++)
            a = ffma2(kr[u], wbuf[(15 + j - u) & 15], a);
        op[(size_t)(t0 + j) * S] = a;
    }
}

// ---------------------------------------------------------------------------
extern "C" void kernel_launch(void* const* d_in, const int* in_sizes, int n_in,
                              void* d_out, int out_size) {
    const float* x     = (const float*)d_in[0];   // (4, 2048, 1024)
    const float* W_B   = (const float*)d_in[1];   // (64, 1024)
    const float* b_B   = (const float*)d_in[2];   // (64,)
    const float* C     = (const float*)d_in[3];   // (64, 1024)
    const float* D     = (const float*)d_in[4];   // (1024,)
    const float* log_A = (const float*)d_in[5];   // (64,)
    float* out = (float*)d_out;

    s4_k12<<<dim3(16, 16), 256>>>(x, W_B, b_B, C, log_A);

    // K3 (PDL secondary to K12; plain fallback)
    cudaLaunchAttribute attr[1];
    attr[0].id = cudaLaunchAttributeProgrammaticStreamSerialization;
    attr[0].val.programmaticStreamSerializationAllowed = 1;

    cudaLaunchConfig_t cfg = {};
    cfg.gridDim  = dim3(2, 64, 4);
    cfg.blockDim = dim3(256, 1, 1);
    cfg.stream = 0;
    cfg.attrs = attr;
    cfg.numAttrs = 1;
    cudaError_t e = cudaLaunchKernelEx(&cfg, s4_k3, x, D, (float*)out);
    if (e != cudaSuccess) {
        (void)cudaGetLastError();
        s4_k3<<<dim3(2, 64, 4), 256>>>(x, D, out);
    }
}